// round 2
// baseline (speedup 1.0000x reference)
#include <cuda_runtime.h>
#include <math.h>

#define CATOM 512
#define NHEADS 8
#define HDIM 64
#define BATCH 2
#define LSEQ 512
#define NATOMS 4
#define SEQ (LSEQ*NATOMS)      /* 2048 */
#define MROWS (BATCH*SEQ)      /* 4096 */
#define FFDIM 2048

// ---------------- scratch (device globals: allocation-free) ----------------
__device__ float g_h [MROWS*CATOM];
__device__ float g_q [MROWS*CATOM];
__device__ float g_k [MROWS*CATOM];
__device__ float g_v [MROWS*CATOM];
__device__ float g_ao[MROWS*CATOM];
__device__ float g_x1[MROWS*CATOM];
__device__ float g_h2[MROWS*CATOM];
__device__ float g_f1[MROWS*FFDIM];

// ---------------- LayerNorm: one block per row, C=512 ----------------
__global__ void __launch_bounds__(256) ln_kernel(const float* __restrict__ x,
                                                 const float* __restrict__ g,
                                                 const float* __restrict__ b,
                                                 float* __restrict__ out) {
    int row = blockIdx.x;
    int tid = threadIdx.x;
    const float* xr = x + (size_t)row * CATOM;
    float v0 = xr[tid];
    float v1 = xr[tid + 256];
    float s  = v0 + v1;
    float sq = v0*v0 + v1*v1;
    #pragma unroll
    for (int o = 16; o > 0; o >>= 1) {
        s  += __shfl_xor_sync(0xffffffffu, s,  o);
        sq += __shfl_xor_sync(0xffffffffu, sq, o);
    }
    __shared__ float ss[8], sqs[8];
    int w = tid >> 5;
    if ((tid & 31) == 0) { ss[w] = s; sqs[w] = sq; }
    __syncthreads();
    float tot = 0.f, totq = 0.f;
    #pragma unroll
    for (int i = 0; i < 8; i++) { tot += ss[i]; totq += sqs[i]; }
    float mu  = tot * (1.0f / CATOM);
    float var = totq * (1.0f / CATOM) - mu * mu;
    float inv = rsqrtf(var + 1e-5f);
    float* orow = out + (size_t)row * CATOM;
    orow[tid]       = (v0 - mu) * inv * g[tid]       + b[tid];
    orow[tid + 256] = (v1 - mu) * inv * g[tid + 256] + b[tid + 256];
}

// ---------------- GEMM: Y[M,N] = A[M,K] @ W[N,K]^T + bias (+epilogue) ------
// mode 0: plain   mode 1: + resid[m,n]   mode 2: gelu(.)
__global__ void __launch_bounds__(256) gemm_nt(const float* __restrict__ A,
                                               const float* __restrict__ Wt,
                                               const float* __restrict__ bias,
                                               const float* __restrict__ resid,
                                               float* __restrict__ Y,
                                               int M, int N, int K, int mode) {
    __shared__ float As[8][132];
    __shared__ float Bs[8][132];
    int m0 = blockIdx.y * 128, n0 = blockIdx.x * 128;
    int tid = threadIdx.x;
    int tx = tid & 15, ty = tid >> 4;

    float acc[8][8];
    #pragma unroll
    for (int i = 0; i < 8; i++)
        #pragma unroll
        for (int j = 0; j < 8; j++) acc[i][j] = 0.f;

    int lr = tid >> 1, lseg = (tid & 1) * 4;
    const float* aptr = A  + (size_t)(m0 + lr) * K + lseg;
    const float* bptr = Wt + (size_t)(n0 + lr) * K + lseg;

    for (int k0 = 0; k0 < K; k0 += 8) {
        float4 av = *(const float4*)(aptr + k0);
        float4 bv = *(const float4*)(bptr + k0);
        __syncthreads();
        As[lseg+0][lr] = av.x; As[lseg+1][lr] = av.y;
        As[lseg+2][lr] = av.z; As[lseg+3][lr] = av.w;
        Bs[lseg+0][lr] = bv.x; Bs[lseg+1][lr] = bv.y;
        Bs[lseg+2][lr] = bv.z; Bs[lseg+3][lr] = bv.w;
        __syncthreads();
        #pragma unroll
        for (int kk = 0; kk < 8; kk++) {
            float4 a0 = *(const float4*)(&As[kk][ty*4]);
            float4 a1 = *(const float4*)(&As[kk][64 + ty*4]);
            float4 b0 = *(const float4*)(&Bs[kk][tx*4]);
            float4 b1 = *(const float4*)(&Bs[kk][64 + tx*4]);
            float af[8] = {a0.x,a0.y,a0.z,a0.w,a1.x,a1.y,a1.z,a1.w};
            float bf[8] = {b0.x,b0.y,b0.z,b0.w,b1.x,b1.y,b1.z,b1.w};
            #pragma unroll
            for (int i = 0; i < 8; i++)
                #pragma unroll
                for (int j = 0; j < 8; j++) acc[i][j] += af[i] * bf[j];
        }
    }

    #pragma unroll
    for (int i = 0; i < 8; i++) {
        int m = m0 + ((i < 4) ? (ty*4 + i) : (64 + ty*4 + i - 4));
        #pragma unroll
        for (int j = 0; j < 8; j++) {
            int n = n0 + ((j < 4) ? (tx*4 + j) : (64 + tx*4 + j - 4));
            float v = acc[i][j] + bias[n];
            if (mode == 1) v += resid[(size_t)m * N + n];
            else if (mode == 2) v = 0.5f * v * (1.0f + erff(v * 0.70710678118654752f));
            Y[(size_t)m * N + n] = v;
        }
    }
}

// ---------------- Flash attention: 64-query tiles, D=64 --------------------
// grid: (SEQ/64, BATCH*NHEADS), block 256.  smem: Qs,Kst,Vs,Ps each [64][68].
__global__ void __launch_bounds__(256) attn_kernel(const float* __restrict__ q,
                                                   const float* __restrict__ k,
                                                   const float* __restrict__ v,
                                                   const float* __restrict__ pair_bias,
                                                   const int* __restrict__ mask,
                                                   float* __restrict__ out) {
    extern __shared__ float sm[];
    float* Qs  = sm;               // [64][68], row-major (row=q, col=d)
    float* Kst = sm + 64*68;       // [64][68], TRANSPOSED: Kst[d][key]
    float* Vs  = sm + 2*64*68;     // [64][68], row-major (row=key, col=d)
    float* Ps  = sm + 3*64*68;     // [64][68], row-major (row=q, col=key)

    int q0 = blockIdx.x * 64;
    int bh = blockIdx.y;
    int b = bh >> 3, h = bh & 7;
    int tid = threadIdx.x, tx = tid & 15, ty = tid >> 4;
    const float scale = 0.125f;   // 64^-0.5
    size_t base = (size_t)b * SEQ * CATOM + (size_t)h * HDIM;

    // load Q tile
    #pragma unroll
    for (int i = 0; i < 4; i++) {
        int idx = tid + i * 256;
        int r = idx >> 4, c4 = (idx & 15) * 4;
        float4 t = *(const float4*)(q + base + (size_t)(q0 + r) * CATOM + c4);
        *(float4*)(Qs + r*68 + c4) = t;
    }

    // periodic pair bias: row%4 == rr, col%4 == cc under this mapping
    float bias_r[4][4];
    #pragma unroll
    for (int rr = 0; rr < 4; rr++)
        #pragma unroll
        for (int cc = 0; cc < 4; cc++)
            bias_r[rr][cc] = pair_bias[h*16 + rr*4 + cc];

    float mi[4], li[4], acc[4][4];
    #pragma unroll
    for (int rr = 0; rr < 4; rr++) {
        mi[rr] = -1e30f; li[rr] = 0.f;
        #pragma unroll
        for (int cc = 0; cc < 4; cc++) acc[rr][cc] = 0.f;
    }
    const int* mrow = mask + (size_t)b * LSEQ;   // int32 bool per metadata

    for (int j0 = 0; j0 < SEQ; j0 += 64) {
        __syncthreads();
        #pragma unroll
        for (int i = 0; i < 4; i++) {
            int idx = tid + i * 256;
            int r = idx >> 4, c4 = (idx & 15) * 4;
            float4 kt = *(const float4*)(k + base + (size_t)(j0 + r) * CATOM + c4);
            Kst[(c4+0)*68 + r] = kt.x; Kst[(c4+1)*68 + r] = kt.y;
            Kst[(c4+2)*68 + r] = kt.z; Kst[(c4+3)*68 + r] = kt.w;
            float4 vt = *(const float4*)(v + base + (size_t)(j0 + r) * CATOM + c4);
            *(float4*)(Vs + r*68 + c4) = vt;
        }
        __syncthreads();

        // scores: s[rr][cc] = Q[ty*4+rr] . K[tx*4+cc]
        float s[4][4];
        #pragma unroll
        for (int rr = 0; rr < 4; rr++)
            #pragma unroll
            for (int cc = 0; cc < 4; cc++) s[rr][cc] = 0.f;
        #pragma unroll 4
        for (int d = 0; d < 64; d += 4) {
            float4 kf[4], qf[4];
            #pragma unroll
            for (int dd = 0; dd < 4; dd++) kf[dd] = *(const float4*)(Kst + (d+dd)*68 + tx*4);
            #pragma unroll
            for (int rr = 0; rr < 4; rr++) qf[rr] = *(const float4*)(Qs + (ty*4+rr)*68 + d);
            #pragma unroll
            for (int rr = 0; rr < 4; rr++) {
                s[rr][0] += qf[rr].x*kf[0].x + qf[rr].y*kf[1].x + qf[rr].z*kf[2].x + qf[rr].w*kf[3].x;
                s[rr][1] += qf[rr].x*kf[0].y + qf[rr].y*kf[1].y + qf[rr].z*kf[2].y + qf[rr].w*kf[3].y;
                s[rr][2] += qf[rr].x*kf[0].z + qf[rr].y*kf[1].z + qf[rr].z*kf[2].z + qf[rr].w*kf[3].z;
                s[rr][3] += qf[rr].x*kf[0].w + qf[rr].y*kf[1].w + qf[rr].z*kf[2].w + qf[rr].w*kf[3].w;
            }
        }

        // scale + bias + mask (mask element for key j is mask[j/4], int32)
        float mk[4];
        #pragma unroll
        for (int cc = 0; cc < 4; cc++) {
            int j = j0 + tx*4 + cc;
            mk[cc] = mrow[j >> 2] ? 0.f : -1e30f;
        }
        #pragma unroll
        for (int rr = 0; rr < 4; rr++)
            #pragma unroll
            for (int cc = 0; cc < 4; cc++)
                s[rr][cc] = s[rr][cc] * scale + bias_r[rr][cc] + mk[cc];

        // online softmax per row (row lives in one 16-lane group)
        #pragma unroll
        for (int rr = 0; rr < 4; rr++) {
            float tm = fmaxf(fmaxf(s[rr][0], s[rr][1]), fmaxf(s[rr][2], s[rr][3]));
            #pragma unroll
            for (int o = 8; o > 0; o >>= 1) tm = fmaxf(tm, __shfl_xor_sync(0xffffffffu, tm, o, 16));
            float mnew = fmaxf(mi[rr], tm);
            float corr = __expf(mi[rr] - mnew);
            float p0 = __expf(s[rr][0] - mnew);
            float p1 = __expf(s[rr][1] - mnew);
            float p2 = __expf(s[rr][2] - mnew);
            float p3 = __expf(s[rr][3] - mnew);
            float ls = p0 + p1 + p2 + p3;
            #pragma unroll
            for (int o = 8; o > 0; o >>= 1) ls += __shfl_xor_sync(0xffffffffu, ls, o, 16);
            li[rr] = li[rr] * corr + ls;
            mi[rr] = mnew;
            #pragma unroll
            for (int cc = 0; cc < 4; cc++) acc[rr][cc] *= corr;
            *(float4*)(Ps + (ty*4+rr)*68 + tx*4) = make_float4(p0, p1, p2, p3);
        }
        __syncwarp();   // Ps rows are written & read by the same 16-lane group

        // O += P @ V : out cols tx*4..+3
        #pragma unroll 4
        for (int c = 0; c < 64; c += 4) {
            float4 vf[4], pf[4];
            #pragma unroll
            for (int i = 0; i < 4; i++) vf[i] = *(const float4*)(Vs + (c+i)*68 + tx*4);
            #pragma unroll
            for (int rr = 0; rr < 4; rr++) pf[rr] = *(const float4*)(Ps + (ty*4+rr)*68 + c);
            #pragma unroll
            for (int rr = 0; rr < 4; rr++) {
                acc[rr][0] += pf[rr].x*vf[0].x + pf[rr].y*vf[1].x + pf[rr].z*vf[2].x + pf[rr].w*vf[3].x;
                acc[rr][1] += pf[rr].x*vf[0].y + pf[rr].y*vf[1].y + pf[rr].z*vf[2].y + pf[rr].w*vf[3].y;
                acc[rr][2] += pf[rr].x*vf[0].z + pf[rr].y*vf[1].z + pf[rr].z*vf[2].z + pf[rr].w*vf[3].z;
                acc[rr][3] += pf[rr].x*vf[0].w + pf[rr].y*vf[1].w + pf[rr].z*vf[2].w + pf[rr].w*vf[3].w;
            }
        }
    }

    // write normalized output
    #pragma unroll
    for (int rr = 0; rr < 4; rr++) {
        float inv = 1.0f / li[rr];
        float4 ov = make_float4(acc[rr][0]*inv, acc[rr][1]*inv, acc[rr][2]*inv, acc[rr][3]*inv);
        *(float4*)(out + base + (size_t)(q0 + ty*4 + rr) * CATOM + tx*4) = ov;
    }
}

// ---------------- driver ----------------
extern "C" void kernel_launch(void* const* d_in, const int* in_sizes, int n_in,
                              void* d_out, int out_size) {
    const float* atom = (const float*)d_in[0];
    const int* mask = (const int*)d_in[1];
    const float* ln1g = (const float*)d_in[2];
    const float* ln1b = (const float*)d_in[3];
    const float* Wq = (const float*)d_in[4];
    const float* bq = (const float*)d_in[5];
    const float* Wk = (const float*)d_in[6];
    const float* bk = (const float*)d_in[7];
    const float* Wv = (const float*)d_in[8];
    const float* bv = (const float*)d_in[9];
    const float* Wo = (const float*)d_in[10];
    const float* bo = (const float*)d_in[11];
    const float* pb = (const float*)d_in[12];
    const float* ln2g = (const float*)d_in[13];
    const float* ln2b = (const float*)d_in[14];
    const float* W1 = (const float*)d_in[15];
    const float* b1 = (const float*)d_in[16];
    const float* W2 = (const float*)d_in[17];
    const float* b2 = (const float*)d_in[18];
    float* out = (float*)d_out;

    float *h_, *q_, *k_, *v_, *ao_, *x1_, *h2_, *f1_;
    cudaGetSymbolAddress((void**)&h_,  g_h);
    cudaGetSymbolAddress((void**)&q_,  g_q);
    cudaGetSymbolAddress((void**)&k_,  g_k);
    cudaGetSymbolAddress((void**)&v_,  g_v);
    cudaGetSymbolAddress((void**)&ao_, g_ao);
    cudaGetSymbolAddress((void**)&x1_, g_x1);
    cudaGetSymbolAddress((void**)&h2_, g_h2);
    cudaGetSymbolAddress((void**)&f1_, g_f1);

    cudaFuncSetAttribute(attn_kernel, cudaFuncAttributeMaxDynamicSharedMemorySize, 4*64*68*4);

    // 1) h = LN1(x)
    ln_kernel<<<MROWS, 256>>>(atom, ln1g, ln1b, h_);
    // 2) q,k,v
    gemm_nt<<<dim3(CATOM/128, MROWS/128), 256>>>(h_, Wq, bq, nullptr, q_, MROWS, CATOM, CATOM, 0);
    gemm_nt<<<dim3(CATOM/128, MROWS/128), 256>>>(h_, Wk, bk, nullptr, k_, MROWS, CATOM, CATOM, 0);
    gemm_nt<<<dim3(CATOM/128, MROWS/128), 256>>>(h_, Wv, bv, nullptr, v_, MROWS, CATOM, CATOM, 0);
    // 3) attention
    attn_kernel<<<dim3(SEQ/64, BATCH*NHEADS), 256, 4*64*68*4>>>(q_, k_, v_, pb, mask, ao_);
    // 4) x1 = x + ao @ Wo^T + bo
    gemm_nt<<<dim3(CATOM/128, MROWS/128), 256>>>(ao_, Wo, bo, atom, x1_, MROWS, CATOM, CATOM, 1);
    // 5) h2 = LN2(x1)
    ln_kernel<<<MROWS, 256>>>(x1_, ln2g, ln2b, h2_);
    // 6) f1 = gelu(h2 @ W1^T + b1)
    gemm_nt<<<dim3(FFDIM/128, MROWS/128), 256>>>(h2_, W1, b1, nullptr, f1_, MROWS, FFDIM, CATOM, 2);
    // 7) out = x1 + f1 @ W2^T + b2
    gemm_nt<<<dim3(CATOM/128, MROWS/128), 256>>>(f1_, W2, b2, x1_, out, MROWS, CATOM, FFDIM, 1);
}

// round 4
// speedup vs baseline: 1.4190x; 1.4190x over previous
#include <cuda_runtime.h>
#include <cuda_bf16.h>
#include <math.h>
#include <stdint.h>

#define CATOM 512
#define NHEADS 8
#define HDIM 64
#define BATCH 2
#define LSEQ 512
#define NATOMS 4
#define SEQ (LSEQ*NATOMS)      /* 2048 */
#define MROWS (BATCH*SEQ)      /* 4096 */
#define FFDIM 2048

// ---------------- scratch (device globals: allocation-free) ----------------
__device__ __nv_bfloat16 g_hh [MROWS*CATOM], g_hl [MROWS*CATOM];
__device__ float         g_q  [MROWS*CATOM];
__device__ float         g_k  [MROWS*CATOM];
__device__ float         g_v  [MROWS*CATOM];
__device__ __nv_bfloat16 g_aoh[MROWS*CATOM], g_aol[MROWS*CATOM];
__device__ float         g_x1 [MROWS*CATOM];
__device__ __nv_bfloat16 g_h2h[MROWS*CATOM], g_h2l[MROWS*CATOM];
__device__ __nv_bfloat16 g_f1h[MROWS*FFDIM], g_f1l[MROWS*FFDIM];
#define WOFF_Q 0
#define WOFF_K (CATOM*CATOM)
#define WOFF_V (2*CATOM*CATOM)
#define WOFF_O (3*CATOM*CATOM)
#define WOFF_1 (4*CATOM*CATOM)
#define WOFF_2 (4*CATOM*CATOM + FFDIM*CATOM)
#define WTOT   (4*CATOM*CATOM + 2*FFDIM*CATOM)
__device__ __nv_bfloat16 g_wh[WTOT], g_wl[WTOT];

// ======================= mma.sync helpers =======================
__device__ __forceinline__ uint32_t smem_u32(const void* p) {
    uint32_t a;
    asm("{ .reg .u64 t; cvta.to.shared.u64 t, %1; cvt.u32.u64 %0, t; }" : "=r"(a) : "l"(p));
    return a;
}
__device__ __forceinline__ void ldm_x4(uint32_t* r, uint32_t addr) {
    asm volatile("ldmatrix.sync.aligned.m8n8.x4.shared.b16 {%0,%1,%2,%3}, [%4];"
        : "=r"(r[0]), "=r"(r[1]), "=r"(r[2]), "=r"(r[3]) : "r"(addr));
}
__device__ __forceinline__ void mma_bf16(float* d, const uint32_t* a, uint32_t b0, uint32_t b1) {
    asm volatile("mma.sync.aligned.m16n8k16.row.col.f32.bf16.bf16.f32 "
        "{%0,%1,%2,%3}, {%4,%5,%6,%7}, {%8,%9}, {%0,%1,%2,%3};"
        : "+f"(d[0]), "+f"(d[1]), "+f"(d[2]), "+f"(d[3])
        : "r"(a[0]), "r"(a[1]), "r"(a[2]), "r"(a[3]), "r"(b0), "r"(b1));
}

// ======================= weight hi/lo split =======================
__global__ void __launch_bounds__(256) split_kernel(const float* __restrict__ x,
                                                    __nv_bfloat16* __restrict__ hi,
                                                    __nv_bfloat16* __restrict__ lo, int n4) {
    int i = blockIdx.x * blockDim.x + threadIdx.x;
    if (i >= n4) return;
    float4 v = ((const float4*)x)[i];
    __nv_bfloat16 h0 = __float2bfloat16(v.x), h1 = __float2bfloat16(v.y);
    __nv_bfloat16 h2 = __float2bfloat16(v.z), h3 = __float2bfloat16(v.w);
    hi[i*4+0] = h0; hi[i*4+1] = h1; hi[i*4+2] = h2; hi[i*4+3] = h3;
    lo[i*4+0] = __float2bfloat16(v.x - __bfloat162float(h0));
    lo[i*4+1] = __float2bfloat16(v.y - __bfloat162float(h1));
    lo[i*4+2] = __float2bfloat16(v.z - __bfloat162float(h2));
    lo[i*4+3] = __float2bfloat16(v.w - __bfloat162float(h3));
}

// ======================= LayerNorm -> bf16 hi/lo =======================
__global__ void __launch_bounds__(256) ln_split_kernel(const float* __restrict__ x,
                                                       const float* __restrict__ g,
                                                       const float* __restrict__ b,
                                                       __nv_bfloat16* __restrict__ hi,
                                                       __nv_bfloat16* __restrict__ lo) {
    int row = blockIdx.x, tid = threadIdx.x;
    const float* xr = x + (size_t)row * CATOM;
    float v0 = xr[tid], v1 = xr[tid + 256];
    float s = v0 + v1, sq = v0*v0 + v1*v1;
    #pragma unroll
    for (int o = 16; o > 0; o >>= 1) {
        s  += __shfl_xor_sync(0xffffffffu, s,  o);
        sq += __shfl_xor_sync(0xffffffffu, sq, o);
    }
    __shared__ float ss[8], sqs[8];
    int w = tid >> 5;
    if ((tid & 31) == 0) { ss[w] = s; sqs[w] = sq; }
    __syncthreads();
    float tot = 0.f, totq = 0.f;
    #pragma unroll
    for (int i = 0; i < 8; i++) { tot += ss[i]; totq += sqs[i]; }
    float mu = tot * (1.0f/CATOM);
    float inv = rsqrtf(totq * (1.0f/CATOM) - mu*mu + 1e-5f);
    size_t o0 = (size_t)row * CATOM;
    float y0 = (v0 - mu) * inv * g[tid] + b[tid];
    float y1 = (v1 - mu) * inv * g[tid+256] + b[tid+256];
    __nv_bfloat16 h0 = __float2bfloat16(y0), h1 = __float2bfloat16(y1);
    hi[o0 + tid] = h0;       lo[o0 + tid]       = __float2bfloat16(y0 - __bfloat162float(h0));
    hi[o0 + tid + 256] = h1; lo[o0 + tid + 256] = __float2bfloat16(y1 - __bfloat162float(h1));
}

// ======================= mma.sync GEMM: Y = A @ W^T (+bias, +epi) ==========
// A: [M,K] bf16 hi/lo, W: [N,K] bf16 hi/lo. 3-term split, fp32 register acc.
// mode 0: Yf = .+bias    mode 1: Yf = .+bias+resid    mode 2: (Yh,Yl)=gelu(.+bias)
#define KC 32
#define LDS 40   /* smem pitch in bf16 elems: 80 bytes -> conflict-free ldmatrix */

__global__ void __launch_bounds__(256)
gemm_mma(const __nv_bfloat16* __restrict__ Ah, const __nv_bfloat16* __restrict__ Al,
         const __nv_bfloat16* __restrict__ Bh, const __nv_bfloat16* __restrict__ Bl,
         const float* __restrict__ bias, const float* __restrict__ resid,
         float* __restrict__ Yf, __nv_bfloat16* __restrict__ Yh, __nv_bfloat16* __restrict__ Yl,
         int M, int N, int K, int mode) {
    __shared__ __align__(16) __nv_bfloat16 sAh[128*LDS], sAl[128*LDS];
    __shared__ __align__(16) __nv_bfloat16 sBh[128*LDS], sBl[128*LDS];

    int tid = threadIdx.x, wid = tid >> 5, lane = tid & 31;
    int n0 = blockIdx.x * 128, m0 = blockIdx.y * 128;
    int wr = wid >> 1, wc = wid & 1;         // 4x2 warp grid
    int mb = wr * 32, nb = wc * 64;          // warp tile 32x64

    float acc[2][8][4];
    #pragma unroll
    for (int mt = 0; mt < 2; mt++)
        #pragma unroll
        for (int nt = 0; nt < 8; nt++)
            #pragma unroll
            for (int i = 0; i < 4; i++) acc[mt][nt][i] = 0.f;

    // ldmatrix base addresses (lane-mapped): row = lane%16, col byte off = (lane/16)*16
    int lrow = lane & 15, lcol = (lane >> 4) * 8;   // lcol in elems

    for (int k0 = 0; k0 < K; k0 += KC) {
        __syncthreads();
        #pragma unroll
        for (int t = 0; t < 2; t++) {
            int idx = tid + t * 256;          // 0..511
            int r = idx >> 2, seg = (idx & 3) * 8;
            size_t ga = (size_t)(m0 + r) * K + k0 + seg;
            size_t gb = (size_t)(n0 + r) * K + k0 + seg;
            *(uint4*)(sAh + r*LDS + seg) = *(const uint4*)(Ah + ga);
            *(uint4*)(sAl + r*LDS + seg) = *(const uint4*)(Al + ga);
            *(uint4*)(sBh + r*LDS + seg) = *(const uint4*)(Bh + gb);
            *(uint4*)(sBl + r*LDS + seg) = *(const uint4*)(Bl + gb);
        }
        __syncthreads();

        #pragma unroll
        for (int ks = 0; ks < 2; ks++) {
            uint32_t ah[2][4], al[2][4];
            #pragma unroll
            for (int mt = 0; mt < 2; mt++) {
                int row = mb + mt*16 + lrow, col = ks*16 + lcol;
                ldm_x4(ah[mt], smem_u32(sAh + row*LDS + col));
                ldm_x4(al[mt], smem_u32(sAl + row*LDS + col));
            }
            #pragma unroll
            for (int nbk = 0; nbk < 4; nbk++) {      // each covers 2 n-tiles
                uint32_t bh[4], bl[4];
                int row = nb + nbk*16 + lrow, col = ks*16 + lcol;
                ldm_x4(bh, smem_u32(sBh + row*LDS + col));
                ldm_x4(bl, smem_u32(sBl + row*LDS + col));
                #pragma unroll
                for (int wch = 0; wch < 2; wch++) {
                    int nt = nbk*2 + wch;
                    #pragma unroll
                    for (int mt = 0; mt < 2; mt++) {
                        mma_bf16(acc[mt][nt], ah[mt], bh[wch], bh[wch+2]);
                        mma_bf16(acc[mt][nt], ah[mt], bl[wch], bl[wch+2]);
                        mma_bf16(acc[mt][nt], al[mt], bh[wch], bh[wch+2]);
                    }
                }
            }
        }
    }

    // epilogue: d0,d1 -> (row g, cols 2t,2t+1); d2,d3 -> (row g+8)
    int g = lane >> 2, tig = lane & 3;
    #pragma unroll
    for (int mt = 0; mt < 2; mt++) {
        #pragma unroll
        for (int half = 0; half < 2; half++) {
            int m = m0 + mb + mt*16 + g + half*8;
            size_t mrow = (size_t)m * N;
            #pragma unroll
            for (int nt = 0; nt < 8; nt++) {
                int n = n0 + nb + nt*8 + tig*2;
                float v0 = acc[mt][nt][half*2+0] + bias[n];
                float v1 = acc[mt][nt][half*2+1] + bias[n+1];
                if (mode == 2) {
                    v0 = 0.5f * v0 * (1.0f + erff(v0 * 0.70710678118654752f));
                    v1 = 0.5f * v1 * (1.0f + erff(v1 * 0.70710678118654752f));
                    __nv_bfloat16 h0 = __float2bfloat16(v0), h1 = __float2bfloat16(v1);
                    Yh[mrow + n]   = h0; Yl[mrow + n]   = __float2bfloat16(v0 - __bfloat162float(h0));
                    Yh[mrow + n+1] = h1; Yl[mrow + n+1] = __float2bfloat16(v1 - __bfloat162float(h1));
                } else {
                    if (mode == 1) {
                        float2 rv = *(const float2*)(resid + mrow + n);
                        v0 += rv.x; v1 += rv.y;
                    }
                    *(float2*)(Yf + mrow + n) = make_float2(v0, v1);
                }
            }
        }
    }
}

// ---------------- Flash attention (fp32 SIMT), outputs bf16 hi/lo ----------
__global__ void __launch_bounds__(256) attn_kernel(const float* __restrict__ q,
                                                   const float* __restrict__ k,
                                                   const float* __restrict__ v,
                                                   const float* __restrict__ pair_bias,
                                                   const int* __restrict__ mask,
                                                   __nv_bfloat16* __restrict__ outh,
                                                   __nv_bfloat16* __restrict__ outl) {
    extern __shared__ float sm[];
    float* Qs  = sm;
    float* Kst = sm + 64*68;
    float* Vs  = sm + 2*64*68;
    float* Ps  = sm + 3*64*68;

    int q0 = blockIdx.x * 64;
    int bh = blockIdx.y;
    int b = bh >> 3, h = bh & 7;
    int tid = threadIdx.x, tx = tid & 15, ty = tid >> 4;
    const float scale = 0.125f;
    size_t base = (size_t)b * SEQ * CATOM + (size_t)h * HDIM;

    #pragma unroll
    for (int i = 0; i < 4; i++) {
        int idx = tid + i * 256;
        int r = idx >> 4, c4 = (idx & 15) * 4;
        float4 t = *(const float4*)(q + base + (size_t)(q0 + r) * CATOM + c4);
        *(float4*)(Qs + r*68 + c4) = t;
    }

    float bias_r[4][4];
    #pragma unroll
    for (int rr = 0; rr < 4; rr++)
        #pragma unroll
        for (int cc = 0; cc < 4; cc++)
            bias_r[rr][cc] = pair_bias[h*16 + rr*4 + cc];

    float mi[4], li[4], acc[4][4];
    #pragma unroll
    for (int rr = 0; rr < 4; rr++) {
        mi[rr] = -1e30f; li[rr] = 0.f;
        #pragma unroll
        for (int cc = 0; cc < 4; cc++) acc[rr][cc] = 0.f;
    }
    const int* mrow = mask + (size_t)b * LSEQ;

    for (int j0 = 0; j0 < SEQ; j0 += 64) {
        __syncthreads();
        #pragma unroll
        for (int i = 0; i < 4; i++) {
            int idx = tid + i * 256;
            int r = idx >> 4, c4 = (idx & 15) * 4;
            float4 kt = *(const float4*)(k + base + (size_t)(j0 + r) * CATOM + c4);
            Kst[(c4+0)*68 + r] = kt.x; Kst[(c4+1)*68 + r] = kt.y;
            Kst[(c4+2)*68 + r] = kt.z; Kst[(c4+3)*68 + r] = kt.w;
            float4 vt = *(const float4*)(v + base + (size_t)(j0 + r) * CATOM + c4);
            *(float4*)(Vs + r*68 + c4) = vt;
        }
        __syncthreads();

        float s[4][4];
        #pragma unroll
        for (int rr = 0; rr < 4; rr++)
            #pragma unroll
            for (int cc = 0; cc < 4; cc++) s[rr][cc] = 0.f;
        #pragma unroll 4
        for (int d = 0; d < 64; d += 4) {
            float4 kf[4], qf[4];
            #pragma unroll
            for (int dd = 0; dd < 4; dd++) kf[dd] = *(const float4*)(Kst + (d+dd)*68 + tx*4);
            #pragma unroll
            for (int rr = 0; rr < 4; rr++) qf[rr] = *(const float4*)(Qs + (ty*4+rr)*68 + d);
            #pragma unroll
            for (int rr = 0; rr < 4; rr++) {
                s[rr][0] += qf[rr].x*kf[0].x + qf[rr].y*kf[1].x + qf[rr].z*kf[2].x + qf[rr].w*kf[3].x;
                s[rr][1] += qf[rr].x*kf[0].y + qf[rr].y*kf[1].y + qf[rr].z*kf[2].y + qf[rr].w*kf[3].y;
                s[rr][2] += qf[rr].x*kf[0].z + qf[rr].y*kf[1].z + qf[rr].z*kf[2].z + qf[rr].w*kf[3].z;
                s[rr][3] += qf[rr].x*kf[0].w + qf[rr].y*kf[1].w + qf[rr].z*kf[2].w + qf[rr].w*kf[3].w;
            }
        }

        float mk[4];
        #pragma unroll
        for (int cc = 0; cc < 4; cc++) {
            int j = j0 + tx*4 + cc;
            mk[cc] = mrow[j >> 2] ? 0.f : -1e30f;
        }
        #pragma unroll
        for (int rr = 0; rr < 4; rr++)
            #pragma unroll
            for (int cc = 0; cc < 4; cc++)
                s[rr][cc] = s[rr][cc] * scale + bias_r[rr][cc] + mk[cc];

        #pragma unroll
        for (int rr = 0; rr < 4; rr++) {
            float tm = fmaxf(fmaxf(s[rr][0], s[rr][1]), fmaxf(s[rr][2], s[rr][3]));
            #pragma unroll
            for (int o = 8; o > 0; o >>= 1) tm = fmaxf(tm, __shfl_xor_sync(0xffffffffu, tm, o, 16));
            float mnew = fmaxf(mi[rr], tm);
            float corr = __expf(mi[rr] - mnew);
            float p0 = __expf(s[rr][0] - mnew);
            float p1 = __expf(s[rr][1] - mnew);
            float p2 = __expf(s[rr][2] - mnew);
            float p3 = __expf(s[rr][3] - mnew);
            float ls = p0 + p1 + p2 + p3;
            #pragma unroll
            for (int o = 8; o > 0; o >>= 1) ls += __shfl_xor_sync(0xffffffffu, ls, o, 16);
            li[rr] = li[rr] * corr + ls;
            mi[rr] = mnew;
            #pragma unroll
            for (int cc = 0; cc < 4; cc++) acc[rr][cc] *= corr;
            *(float4*)(Ps + (ty*4+rr)*68 + tx*4) = make_float4(p0, p1, p2, p3);
        }
        __syncwarp();

        #pragma unroll 4
        for (int c = 0; c < 64; c += 4) {
            float4 vf[4], pf[4];
            #pragma unroll
            for (int i = 0; i < 4; i++) vf[i] = *(const float4*)(Vs + (c+i)*68 + tx*4);
            #pragma unroll
            for (int rr = 0; rr < 4; rr++) pf[rr] = *(const float4*)(Ps + (ty*4+rr)*68 + c);
            #pragma unroll
            for (int rr = 0; rr < 4; rr++) {
                acc[rr][0] += pf[rr].x*vf[0].x + pf[rr].y*vf[1].x + pf[rr].z*vf[2].x + pf[rr].w*vf[3].x;
                acc[rr][1] += pf[rr].x*vf[0].y + pf[rr].y*vf[1].y + pf[rr].z*vf[2].y + pf[rr].w*vf[3].y;
                acc[rr][2] += pf[rr].x*vf[0].z + pf[rr].y*vf[1].z + pf[rr].z*vf[2].z + pf[rr].w*vf[3].z;
                acc[rr][3] += pf[rr].x*vf[0].w + pf[rr].y*vf[1].w + pf[rr].z*vf[2].w + pf[rr].w*vf[3].w;
            }
        }
    }

    #pragma unroll
    for (int rr = 0; rr < 4; rr++) {
        float inv = 1.0f / li[rr];
        size_t o = base + (size_t)(q0 + ty*4 + rr) * CATOM + tx*4;
        #pragma unroll
        for (int cc = 0; cc < 4; cc++) {
            float val = acc[rr][cc] * inv;
            __nv_bfloat16 hh = __float2bfloat16(val);
            outh[o + cc] = hh;
            outl[o + cc] = __float2bfloat16(val - __bfloat162float(hh));
        }
    }
}

// ---------------- driver ----------------
extern "C" void kernel_launch(void* const* d_in, const int* in_sizes, int n_in,
                              void* d_out, int out_size) {
    const float* atom = (const float*)d_in[0];
    const int* mask = (const int*)d_in[1];
    const float* ln1g = (const float*)d_in[2];
    const float* ln1b = (const float*)d_in[3];
    const float* Wq = (const float*)d_in[4];
    const float* bq = (const float*)d_in[5];
    const float* Wk = (const float*)d_in[6];
    const float* bk = (const float*)d_in[7];
    const float* Wv = (const float*)d_in[8];
    const float* bv = (const float*)d_in[9];
    const float* Wo = (const float*)d_in[10];
    const float* bo = (const float*)d_in[11];
    const float* pb = (const float*)d_in[12];
    const float* ln2g = (const float*)d_in[13];
    const float* ln2b = (const float*)d_in[14];
    const float* W1 = (const float*)d_in[15];
    const float* b1 = (const float*)d_in[16];
    const float* W2 = (const float*)d_in[17];
    const float* b2 = (const float*)d_in[18];
    float* out = (float*)d_out;

    __nv_bfloat16 *hh_, *hl_, *aoh_, *aol_, *h2h_, *h2l_, *f1h_, *f1l_, *wh_, *wl_;
    float *q_, *k_, *v_, *x1_;
    cudaGetSymbolAddress((void**)&hh_,  g_hh);  cudaGetSymbolAddress((void**)&hl_,  g_hl);
    cudaGetSymbolAddress((void**)&q_,   g_q);   cudaGetSymbolAddress((void**)&k_,   g_k);
    cudaGetSymbolAddress((void**)&v_,   g_v);
    cudaGetSymbolAddress((void**)&aoh_, g_aoh); cudaGetSymbolAddress((void**)&aol_, g_aol);
    cudaGetSymbolAddress((void**)&x1_,  g_x1);
    cudaGetSymbolAddress((void**)&h2h_, g_h2h); cudaGetSymbolAddress((void**)&h2l_, g_h2l);
    cudaGetSymbolAddress((void**)&f1h_, g_f1h); cudaGetSymbolAddress((void**)&f1l_, g_f1l);
    cudaGetSymbolAddress((void**)&wh_,  g_wh);  cudaGetSymbolAddress((void**)&wl_,  g_wl);

    cudaFuncSetAttribute(attn_kernel, cudaFuncAttributeMaxDynamicSharedMemorySize, 4*64*68*4);

    // weight splits
    split_kernel<<<(CATOM*CATOM/4 + 255)/256, 256>>>(Wq, wh_ + WOFF_Q, wl_ + WOFF_Q, CATOM*CATOM/4);
    split_kernel<<<(CATOM*CATOM/4 + 255)/256, 256>>>(Wk, wh_ + WOFF_K, wl_ + WOFF_K, CATOM*CATOM/4);
    split_kernel<<<(CATOM*CATOM/4 + 255)/256, 256>>>(Wv, wh_ + WOFF_V, wl_ + WOFF_V, CATOM*CATOM/4);
    split_kernel<<<(CATOM*CATOM/4 + 255)/256, 256>>>(Wo, wh_ + WOFF_O, wl_ + WOFF_O, CATOM*CATOM/4);
    split_kernel<<<(FFDIM*CATOM/4 + 255)/256, 256>>>(W1, wh_ + WOFF_1, wl_ + WOFF_1, FFDIM*CATOM/4);
    split_kernel<<<(FFDIM*CATOM/4 + 255)/256, 256>>>(W2, wh_ + WOFF_2, wl_ + WOFF_2, FFDIM*CATOM/4);

    // 1) h = LN1(x) -> bf16 hi/lo
    ln_split_kernel<<<MROWS, 256>>>(atom, ln1g, ln1b, hh_, hl_);
    // 2) q,k,v (fp32 out)
    gemm_mma<<<dim3(CATOM/128, MROWS/128), 256>>>(hh_, hl_, wh_+WOFF_Q, wl_+WOFF_Q, bq, nullptr, q_, nullptr, nullptr, MROWS, CATOM, CATOM, 0);
    gemm_mma<<<dim3(CATOM/128, MROWS/128), 256>>>(hh_, hl_, wh_+WOFF_K, wl_+WOFF_K, bk, nullptr, k_, nullptr, nullptr, MROWS, CATOM, CATOM, 0);
    gemm_mma<<<dim3(CATOM/128, MROWS/128), 256>>>(hh_, hl_, wh_+WOFF_V, wl_+WOFF_V, bv, nullptr, v_, nullptr, nullptr, MROWS, CATOM, CATOM, 0);
    // 3) attention -> ao bf16 hi/lo
    attn_kernel<<<dim3(SEQ/64, BATCH*NHEADS), 256, 4*64*68*4>>>(q_, k_, v_, pb, mask, aoh_, aol_);
    // 4) x1 = x + ao @ Wo^T + bo   (fp32)
    gemm_mma<<<dim3(CATOM/128, MROWS/128), 256>>>(aoh_, aol_, wh_+WOFF_O, wl_+WOFF_O, bo, atom, x1_, nullptr, nullptr, MROWS, CATOM, CATOM, 1);
    // 5) h2 = LN2(x1) -> bf16 hi/lo
    ln_split_kernel<<<MROWS, 256>>>(x1_, ln2g, ln2b, h2h_, h2l_);
    // 6) f1 = gelu(h2 @ W1^T + b1) -> bf16 hi/lo
    gemm_mma<<<dim3(FFDIM/128, MROWS/128), 256>>>(h2h_, h2l_, wh_+WOFF_1, wl_+WOFF_1, b1, nullptr, nullptr, f1h_, f1l_, MROWS, FFDIM, CATOM, 2);
    // 7) out = x1 + f1 @ W2^T + b2  (fp32 to d_out)
    gemm_mma<<<dim3(CATOM/128, MROWS/128), 256>>>(f1h_, f1l_, wh_+WOFF_2, wl_+WOFF_2, b2, x1_, out, nullptr, nullptr, MROWS, CATOM, FFDIM, 1);
}

// round 6
// speedup vs baseline: 2.9379x; 2.0704x over previous
#include <cuda_runtime.h>
#include <cuda_bf16.h>
#include <math.h>
#include <stdint.h>

#define CATOM 512
#define NHEADS 8
#define HDIM 64
#define BATCH 2
#define LSEQ 512
#define NATOMS 4
#define SEQ (LSEQ*NATOMS)      /* 2048 */
#define MROWS (BATCH*SEQ)      /* 4096 */
#define FFDIM 2048

// ---------------- scratch (device globals: allocation-free) ----------------
__device__ __nv_bfloat16 g_hh [MROWS*CATOM];
__device__ __nv_bfloat16 g_qb [MROWS*CATOM];
__device__ __nv_bfloat16 g_kb [MROWS*CATOM];
__device__ __nv_bfloat16 g_vb [MROWS*CATOM];
__device__ __nv_bfloat16 g_aoh[MROWS*CATOM];
__device__ float         g_x1 [MROWS*CATOM];
__device__ __nv_bfloat16 g_h2h[MROWS*CATOM], g_h2l[MROWS*CATOM];
__device__ __nv_bfloat16 g_f1h[MROWS*FFDIM], g_f1l[MROWS*FFDIM];
#define WOFF_Q 0
#define WOFF_K (CATOM*CATOM)
#define WOFF_V (2*CATOM*CATOM)
#define WOFF_O (3*CATOM*CATOM)
#define WOFF_1 (4*CATOM*CATOM)
#define WOFF_2 (4*CATOM*CATOM + FFDIM*CATOM)
#define WTOT   (4*CATOM*CATOM + 2*FFDIM*CATOM)
__device__ __nv_bfloat16 g_wh[WTOT], g_wl[WTOT];

// ======================= mma.sync helpers =======================
__device__ __forceinline__ uint32_t smem_u32(const void* p) {
    uint32_t a;
    asm("{ .reg .u64 t; cvta.to.shared.u64 t, %1; cvt.u32.u64 %0, t; }" : "=r"(a) : "l"(p));
    return a;
}
__device__ __forceinline__ void ldm_x4(uint32_t* r, uint32_t addr) {
    asm volatile("ldmatrix.sync.aligned.m8n8.x4.shared.b16 {%0,%1,%2,%3}, [%4];"
        : "=r"(r[0]), "=r"(r[1]), "=r"(r[2]), "=r"(r[3]) : "r"(addr));
}
__device__ __forceinline__ void ldm_x4_t(uint32_t* r, uint32_t addr) {
    asm volatile("ldmatrix.sync.aligned.m8n8.x4.trans.shared.b16 {%0,%1,%2,%3}, [%4];"
        : "=r"(r[0]), "=r"(r[1]), "=r"(r[2]), "=r"(r[3]) : "r"(addr));
}
__device__ __forceinline__ void mma_bf16(float* d, const uint32_t* a, uint32_t b0, uint32_t b1) {
    asm volatile("mma.sync.aligned.m16n8k16.row.col.f32.bf16.bf16.f32 "
        "{%0,%1,%2,%3}, {%4,%5,%6,%7}, {%8,%9}, {%0,%1,%2,%3};"
        : "+f"(d[0]), "+f"(d[1]), "+f"(d[2]), "+f"(d[3])
        : "r"(a[0]), "r"(a[1]), "r"(a[2]), "r"(a[3]), "r"(b0), "r"(b1));
}
__device__ __forceinline__ uint32_t pack_bf16(float lo, float hi) {
    uint32_t d;
    asm("cvt.rn.bf16x2.f32 %0, %1, %2;" : "=r"(d) : "f"(hi), "f"(lo));
    return d;
}

// ======================= weight hi/lo split =======================
__global__ void __launch_bounds__(256) split_kernel(const float* __restrict__ x,
                                                    __nv_bfloat16* __restrict__ hi,
                                                    __nv_bfloat16* __restrict__ lo, int n4) {
    int i = blockIdx.x * blockDim.x + threadIdx.x;
    if (i >= n4) return;
    float4 v = ((const float4*)x)[i];
    __nv_bfloat16 h0 = __float2bfloat16(v.x), h1 = __float2bfloat16(v.y);
    __nv_bfloat16 h2 = __float2bfloat16(v.z), h3 = __float2bfloat16(v.w);
    hi[i*4+0] = h0; hi[i*4+1] = h1; hi[i*4+2] = h2; hi[i*4+3] = h3;
    lo[i*4+0] = __float2bfloat16(v.x - __bfloat162float(h0));
    lo[i*4+1] = __float2bfloat16(v.y - __bfloat162float(h1));
    lo[i*4+2] = __float2bfloat16(v.z - __bfloat162float(h2));
    lo[i*4+3] = __float2bfloat16(v.w - __bfloat162float(h3));
}

// ======================= LayerNorm -> bf16 (hi, optional lo) ===============
__global__ void __launch_bounds__(256) ln_split_kernel(const float* __restrict__ x,
                                                       const float* __restrict__ g,
                                                       const float* __restrict__ b,
                                                       __nv_bfloat16* __restrict__ hi,
                                                       __nv_bfloat16* __restrict__ lo) {
    int row = blockIdx.x, tid = threadIdx.x;
    const float* xr = x + (size_t)row * CATOM;
    float v0 = xr[tid], v1 = xr[tid + 256];
    float s = v0 + v1, sq = v0*v0 + v1*v1;
    #pragma unroll
    for (int o = 16; o > 0; o >>= 1) {
        s  += __shfl_xor_sync(0xffffffffu, s,  o);
        sq += __shfl_xor_sync(0xffffffffu, sq, o);
    }
    __shared__ float ss[8], sqs[8];
    int w = tid >> 5;
    if ((tid & 31) == 0) { ss[w] = s; sqs[w] = sq; }
    __syncthreads();
    float tot = 0.f, totq = 0.f;
    #pragma unroll
    for (int i = 0; i < 8; i++) { tot += ss[i]; totq += sqs[i]; }
    float mu = tot * (1.0f/CATOM);
    float inv = rsqrtf(totq * (1.0f/CATOM) - mu*mu + 1e-5f);
    size_t o0 = (size_t)row * CATOM;
    float y0 = (v0 - mu) * inv * g[tid] + b[tid];
    float y1 = (v1 - mu) * inv * g[tid+256] + b[tid+256];
    __nv_bfloat16 h0 = __float2bfloat16(y0), h1 = __float2bfloat16(y1);
    hi[o0 + tid] = h0;
    hi[o0 + tid + 256] = h1;
    if (lo) {
        lo[o0 + tid]       = __float2bfloat16(y0 - __bfloat162float(h0));
        lo[o0 + tid + 256] = __float2bfloat16(y1 - __bfloat162float(h1));
    }
}

// ======================= mma.sync GEMM: Y = A @ W^T (+bias, +epi) ==========
// terms==3: AhBh+AhBl+AlBh   terms==2: AhBh+AhBl (Al unused)
// mode 0: Yf=.+bias  1: Yf=.+bias+resid  2: (Yh,Yl)=gelu(.+bias)  3: Yh=bf16(.+bias)
#define KC 32
#define LDS 40

__global__ void __launch_bounds__(256)
gemm_mma(const __nv_bfloat16* __restrict__ Ah, const __nv_bfloat16* __restrict__ Al,
         const __nv_bfloat16* __restrict__ Bh, const __nv_bfloat16* __restrict__ Bl,
         const float* __restrict__ bias, const float* __restrict__ resid,
         float* __restrict__ Yf, __nv_bfloat16* __restrict__ Yh, __nv_bfloat16* __restrict__ Yl,
         int M, int N, int K, int mode, int terms) {
    __shared__ __align__(16) __nv_bfloat16 sAh[128*LDS], sAl[128*LDS];
    __shared__ __align__(16) __nv_bfloat16 sBh[128*LDS], sBl[128*LDS];

    int tid = threadIdx.x, wid = tid >> 5, lane = tid & 31;
    int n0 = blockIdx.x * 128, m0 = blockIdx.y * 128;
    int wr = wid >> 1, wc = wid & 1;
    int mb = wr * 32, nb = wc * 64;

    float acc[2][8][4];
    #pragma unroll
    for (int mt = 0; mt < 2; mt++)
        #pragma unroll
        for (int nt = 0; nt < 8; nt++)
            #pragma unroll
            for (int i = 0; i < 4; i++) acc[mt][nt][i] = 0.f;

    int lrow = lane & 15, lcol = (lane >> 4) * 8;

    for (int k0 = 0; k0 < K; k0 += KC) {
        __syncthreads();
        #pragma unroll
        for (int t = 0; t < 2; t++) {
            int idx = tid + t * 256;
            int r = idx >> 2, seg = (idx & 3) * 8;
            size_t ga = (size_t)(m0 + r) * K + k0 + seg;
            size_t gb = (size_t)(n0 + r) * K + k0 + seg;
            *(uint4*)(sAh + r*LDS + seg) = *(const uint4*)(Ah + ga);
            if (terms == 3) *(uint4*)(sAl + r*LDS + seg) = *(const uint4*)(Al + ga);
            *(uint4*)(sBh + r*LDS + seg) = *(const uint4*)(Bh + gb);
            *(uint4*)(sBl + r*LDS + seg) = *(const uint4*)(Bl + gb);
        }
        __syncthreads();

        #pragma unroll
        for (int ks = 0; ks < 2; ks++) {
            uint32_t ah[2][4], al[2][4];
            #pragma unroll
            for (int mt = 0; mt < 2; mt++) {
                int row = mb + mt*16 + lrow, col = ks*16 + lcol;
                ldm_x4(ah[mt], smem_u32(sAh + row*LDS + col));
                if (terms == 3) ldm_x4(al[mt], smem_u32(sAl + row*LDS + col));
            }
            #pragma unroll
            for (int nbk = 0; nbk < 4; nbk++) {
                uint32_t bh[4], bl[4];
                int row = nb + nbk*16 + lrow, col = ks*16 + lcol;
                ldm_x4(bh, smem_u32(sBh + row*LDS + col));
                ldm_x4(bl, smem_u32(sBl + row*LDS + col));
                #pragma unroll
                for (int wch = 0; wch < 2; wch++) {
                    int nt = nbk*2 + wch;
                    #pragma unroll
                    for (int mt = 0; mt < 2; mt++) {
                        mma_bf16(acc[mt][nt], ah[mt], bh[wch], bh[wch+2]);
                        mma_bf16(acc[mt][nt], ah[mt], bl[wch], bl[wch+2]);
                        if (terms == 3) mma_bf16(acc[mt][nt], al[mt], bh[wch], bh[wch+2]);
                    }
                }
            }
        }
    }

    int g = lane >> 2, tig = lane & 3;
    #pragma unroll
    for (int mt = 0; mt < 2; mt++) {
        #pragma unroll
        for (int half = 0; half < 2; half++) {
            int m = m0 + mb + mt*16 + g + half*8;
            size_t mrow = (size_t)m * N;
            #pragma unroll
            for (int nt = 0; nt < 8; nt++) {
                int n = n0 + nb + nt*8 + tig*2;
                float v0 = acc[mt][nt][half*2+0] + bias[n];
                float v1 = acc[mt][nt][half*2+1] + bias[n+1];
                if (mode == 2) {
                    v0 = 0.5f * v0 * (1.0f + erff(v0 * 0.70710678118654752f));
                    v1 = 0.5f * v1 * (1.0f + erff(v1 * 0.70710678118654752f));
                    __nv_bfloat16 h0 = __float2bfloat16(v0), h1 = __float2bfloat16(v1);
                    Yh[mrow + n]   = h0; Yl[mrow + n]   = __float2bfloat16(v0 - __bfloat162float(h0));
                    Yh[mrow + n+1] = h1; Yl[mrow + n+1] = __float2bfloat16(v1 - __bfloat162float(h1));
                } else if (mode == 3) {
                    __nv_bfloat162 hv;
                    hv.x = __float2bfloat16(v0); hv.y = __float2bfloat16(v1);
                    *(__nv_bfloat162*)(Yh + mrow + n) = hv;
                } else {
                    if (mode == 1) {
                        float2 rv = *(const float2*)(resid + mrow + n);
                        v0 += rv.x; v1 += rv.y;
                    }
                    *(float2*)(Yf + mrow + n) = make_float2(v0, v1);
                }
            }
        }
    }
}

// ================= Flash attention, mma.sync bf16 ==========================
// grid (SEQ/128, B*H), 256 thr (8 warps). Warp w: q rows w*16..w*16+15.
#define AP 72   /* pitch for 64-wide tiles: 144B rows -> conflict-free ldmatrix */
__global__ void __launch_bounds__(256)
attn_mma(const __nv_bfloat16* __restrict__ qb, const __nv_bfloat16* __restrict__ kb,
         const __nv_bfloat16* __restrict__ vb, const float* __restrict__ pair_bias,
         const int* __restrict__ mask, __nv_bfloat16* __restrict__ outb) {
    __shared__ __align__(16) __nv_bfloat16 sQ[128*AP];
    __shared__ __align__(16) __nv_bfloat16 sK[64*AP];
    __shared__ __align__(16) __nv_bfloat16 sV[64*AP];

    int q0 = blockIdx.x * 128;
    int bh = blockIdx.y;
    int b = bh >> 3, h = bh & 7;
    int tid = threadIdx.x, wid = tid >> 5, lane = tid & 31;
    int g = lane >> 2, tig = lane & 3;
    int lrow = lane & 15, lcol = (lane >> 4) * 8;
    const float scale = 0.125f;
    size_t base = (size_t)b * SEQ * CATOM + (size_t)h * HDIM;

    // load Q tile [128][64]
    #pragma unroll
    for (int i = 0; i < 4; i++) {
        int u = tid + i * 256;
        int r = u >> 3, seg = (u & 7) * 8;
        *(uint4*)(sQ + r*AP + seg) = *(const uint4*)(qb + base + (size_t)(q0 + r) * CATOM + seg);
    }
    __syncthreads();

    // hoist Q fragments (loop-invariant)
    uint32_t aQ[4][4];
    #pragma unroll
    for (int ks = 0; ks < 4; ks++)
        ldm_x4(aQ[ks], smem_u32(sQ + (wid*16 + lrow)*AP + ks*16 + lcol));

    // periodic bias: row%4 = g&3 (rows g, g+8 equal mod 4), col%4 = (2tig+c)&3
    float bias2[2];
    bias2[0] = pair_bias[h*16 + (g&3)*4 + ((2*tig)&3)];
    bias2[1] = pair_bias[h*16 + (g&3)*4 + ((2*tig+1)&3)];

    float mi[2] = {-1e30f, -1e30f}, li[2] = {0.f, 0.f};
    float acc[8][4];
    #pragma unroll
    for (int nt = 0; nt < 8; nt++)
        #pragma unroll
        for (int i = 0; i < 4; i++) acc[nt][i] = 0.f;

    const int* mrow = mask + (size_t)b * LSEQ;
    int msel = tig >> 1;
    int vkey = (lane & 7) | ((lane & 16) >> 1);   // key offset within 16-block
    int vcol = lane & 8;                          // dim offset within 16-block

    for (int j0 = 0; j0 < SEQ; j0 += 64) {
        __syncthreads();
        // load K,V tiles [64][64]
        #pragma unroll
        for (int i = 0; i < 2; i++) {
            int u = tid + i * 256;
            int r = u >> 3, seg = (u & 7) * 8;
            size_t gk = base + (size_t)(j0 + r) * CATOM + seg;
            *(uint4*)(sK + r*AP + seg) = *(const uint4*)(kb + gk);
            *(uint4*)(sV + r*AP + seg) = *(const uint4*)(vb + gk);
        }
        __syncthreads();

        // ---- scores: c[nt][*] = Q(16) . K(64 keys) ----
        float c[8][4];
        #pragma unroll
        for (int nt = 0; nt < 8; nt++)
            #pragma unroll
            for (int i = 0; i < 4; i++) c[nt][i] = 0.f;
        #pragma unroll
        for (int nbk = 0; nbk < 4; nbk++) {
            uint32_t bk[4][4];
            #pragma unroll
            for (int ks = 0; ks < 4; ks++)
                ldm_x4(bk[ks], smem_u32(sK + (nbk*16 + lrow)*AP + ks*16 + lcol));
            #pragma unroll
            for (int wch = 0; wch < 2; wch++) {
                float* cc = c[nbk*2 + wch];
                #pragma unroll
                for (int ks = 0; ks < 4; ks++)
                    mma_bf16(cc, aQ[ks], bk[ks][wch], bk[ks][wch+2]);
            }
        }

        // ---- scale + bias + mask ----
        #pragma unroll
        for (int nt = 0; nt < 8; nt++) {
            float mk = mrow[(j0 >> 2) + 2*nt + msel] ? 0.f : -1e30f;
            c[nt][0] = c[nt][0]*scale + bias2[0] + mk;
            c[nt][1] = c[nt][1]*scale + bias2[1] + mk;
            c[nt][2] = c[nt][2]*scale + bias2[0] + mk;
            c[nt][3] = c[nt][3]*scale + bias2[1] + mk;
        }

        // ---- online softmax (2 rows/thread: g and g+8) ----
        float tm0 = -1e30f, tm1 = -1e30f;
        #pragma unroll
        for (int nt = 0; nt < 8; nt++) {
            tm0 = fmaxf(tm0, fmaxf(c[nt][0], c[nt][1]));
            tm1 = fmaxf(tm1, fmaxf(c[nt][2], c[nt][3]));
        }
        #pragma unroll
        for (int o = 1; o <= 2; o <<= 1) {
            tm0 = fmaxf(tm0, __shfl_xor_sync(0xffffffffu, tm0, o));
            tm1 = fmaxf(tm1, __shfl_xor_sync(0xffffffffu, tm1, o));
        }
        float mn0 = fmaxf(mi[0], tm0), mn1 = fmaxf(mi[1], tm1);
        float cor0 = __expf(mi[0] - mn0), cor1 = __expf(mi[1] - mn1);
        float sum0 = 0.f, sum1 = 0.f;
        #pragma unroll
        for (int nt = 0; nt < 8; nt++) {
            c[nt][0] = __expf(c[nt][0] - mn0);
            c[nt][1] = __expf(c[nt][1] - mn0);
            c[nt][2] = __expf(c[nt][2] - mn1);
            c[nt][3] = __expf(c[nt][3] - mn1);
            sum0 += c[nt][0] + c[nt][1];
            sum1 += c[nt][2] + c[nt][3];
        }
        #pragma unroll
        for (int o = 1; o <= 2; o <<= 1) {
            sum0 += __shfl_xor_sync(0xffffffffu, sum0, o);
            sum1 += __shfl_xor_sync(0xffffffffu, sum1, o);
        }
        li[0] = li[0]*cor0 + sum0; li[1] = li[1]*cor1 + sum1;
        mi[0] = mn0; mi[1] = mn1;
        #pragma unroll
        for (int nt = 0; nt < 8; nt++) {
            acc[nt][0] *= cor0; acc[nt][1] *= cor0;
            acc[nt][2] *= cor1; acc[nt][3] *= cor1;
        }

        // ---- pack P into A fragments (keys = k dim) ----
        uint32_t aP[4][4];
        #pragma unroll
        for (int ks = 0; ks < 4; ks++) {
            aP[ks][0] = pack_bf16(c[2*ks][0],   c[2*ks][1]);
            aP[ks][1] = pack_bf16(c[2*ks][2],   c[2*ks][3]);
            aP[ks][2] = pack_bf16(c[2*ks+1][0], c[2*ks+1][1]);
            aP[ks][3] = pack_bf16(c[2*ks+1][2], c[2*ks+1][3]);
        }

        // ---- O += P @ V (B via trans ldmatrix: Vt[dim][key]) ----
        #pragma unroll
        for (int nbk = 0; nbk < 4; nbk++) {
            uint32_t bv[4][4];
            #pragma unroll
            for (int ks = 0; ks < 4; ks++)
                ldm_x4_t(bv[ks], smem_u32(sV + (ks*16 + vkey)*AP + nbk*16 + vcol));
            #pragma unroll
            for (int wch = 0; wch < 2; wch++) {
                float* oo = acc[nbk*2 + wch];
                #pragma unroll
                for (int ks = 0; ks < 4; ks++)
                    mma_bf16(oo, aP[ks], bv[ks][wch], bv[ks][wch+2]);
            }
        }
    }

    // ---- epilogue ----
    float inv0 = 1.0f / li[0], inv1 = 1.0f / li[1];
    #pragma unroll
    for (int nt = 0; nt < 8; nt++) {
        size_t r0 = base + (size_t)(q0 + wid*16 + g) * CATOM + nt*8 + tig*2;
        size_t r1 = r0 + (size_t)8 * CATOM;
        __nv_bfloat162 v0, v1;
        v0.x = __float2bfloat16(acc[nt][0] * inv0);
        v0.y = __float2bfloat16(acc[nt][1] * inv0);
        v1.x = __float2bfloat16(acc[nt][2] * inv1);
        v1.y = __float2bfloat16(acc[nt][3] * inv1);
        *(__nv_bfloat162*)(outb + r0) = v0;
        *(__nv_bfloat162*)(outb + r1) = v1;
    }
}

// ---------------- driver ----------------
extern "C" void kernel_launch(void* const* d_in, const int* in_sizes, int n_in,
                              void* d_out, int out_size) {
    const float* atom = (const float*)d_in[0];
    const int* mask = (const int*)d_in[1];
    const float* ln1g = (const float*)d_in[2];
    const float* ln1b = (const float*)d_in[3];
    const float* Wq = (const float*)d_in[4];
    const float* bq = (const float*)d_in[5];
    const float* Wk = (const float*)d_in[6];
    const float* bk = (const float*)d_in[7];
    const float* Wv = (const float*)d_in[8];
    const float* bv = (const float*)d_in[9];
    const float* Wo = (const float*)d_in[10];
    const float* bo = (const float*)d_in[11];
    const float* pb = (const float*)d_in[12];
    const float* ln2g = (const float*)d_in[13];
    const float* ln2b = (const float*)d_in[14];
    const float* W1 = (const float*)d_in[15];
    const float* b1 = (const float*)d_in[16];
    const float* W2 = (const float*)d_in[17];
    const float* b2 = (const float*)d_in[18];
    float* out = (float*)d_out;

    __nv_bfloat16 *hh_, *qb_, *kb_, *vb_, *aoh_, *h2h_, *h2l_, *f1h_, *f1l_, *wh_, *wl_;
    float *x1_;
    cudaGetSymbolAddress((void**)&hh_,  g_hh);
    cudaGetSymbolAddress((void**)&qb_,  g_qb);
    cudaGetSymbolAddress((void**)&kb_,  g_kb);
    cudaGetSymbolAddress((void**)&vb_,  g_vb);
    cudaGetSymbolAddress((void**)&aoh_, g_aoh);
    cudaGetSymbolAddress((void**)&x1_,  g_x1);
    cudaGetSymbolAddress((void**)&h2h_, g_h2h); cudaGetSymbolAddress((void**)&h2l_, g_h2l);
    cudaGetSymbolAddress((void**)&f1h_, g_f1h); cudaGetSymbolAddress((void**)&f1l_, g_f1l);
    cudaGetSymbolAddress((void**)&wh_,  g_wh);  cudaGetSymbolAddress((void**)&wl_,  g_wl);

    // weight splits
    split_kernel<<<(CATOM*CATOM/4 + 255)/256, 256>>>(Wq, wh_ + WOFF_Q, wl_ + WOFF_Q, CATOM*CATOM/4);
    split_kernel<<<(CATOM*CATOM/4 + 255)/256, 256>>>(Wk, wh_ + WOFF_K, wl_ + WOFF_K, CATOM*CATOM/4);
    split_kernel<<<(CATOM*CATOM/4 + 255)/256, 256>>>(Wv, wh_ + WOFF_V, wl_ + WOFF_V, CATOM*CATOM/4);
    split_kernel<<<(CATOM*CATOM/4 + 255)/256, 256>>>(Wo, wh_ + WOFF_O, wl_ + WOFF_O, CATOM*CATOM/4);
    split_kernel<<<(FFDIM*CATOM/4 + 255)/256, 256>>>(W1, wh_ + WOFF_1, wl_ + WOFF_1, FFDIM*CATOM/4);
    split_kernel<<<(FFDIM*CATOM/4 + 255)/256, 256>>>(W2, wh_ + WOFF_2, wl_ + WOFF_2, FFDIM*CATOM/4);

    // 1) h = LN1(x) -> single bf16
    ln_split_kernel<<<MROWS, 256>>>(atom, ln1g, ln1b, hh_, nullptr);
    // 2) q,k,v bf16 (2-term)
    gemm_mma<<<dim3(CATOM/128, MROWS/128), 256>>>(hh_, nullptr, wh_+WOFF_Q, wl_+WOFF_Q, bq, nullptr, nullptr, qb_, nullptr, MROWS, CATOM, CATOM, 3, 2);
    gemm_mma<<<dim3(CATOM/128, MROWS/128), 256>>>(hh_, nullptr, wh_+WOFF_K, wl_+WOFF_K, bk, nullptr, nullptr, kb_, nullptr, MROWS, CATOM, CATOM, 3, 2);
    gemm_mma<<<dim3(CATOM/128, MROWS/128), 256>>>(hh_, nullptr, wh_+WOFF_V, wl_+WOFF_V, bv, nullptr, nullptr, vb_, nullptr, MROWS, CATOM, CATOM, 3, 2);
    // 3) attention (tensor core)
    attn_mma<<<dim3(SEQ/128, BATCH*NHEADS), 256>>>(qb_, kb_, vb_, pb, mask, aoh_);
    // 4) x1 = x + ao @ Wo^T + bo  (2-term, fp32)
    gemm_mma<<<dim3(CATOM/128, MROWS/128), 256>>>(aoh_, nullptr, wh_+WOFF_O, wl_+WOFF_O, bo, atom, x1_, nullptr, nullptr, MROWS, CATOM, CATOM, 1, 2);
    // 5) h2 = LN2(x1) -> hi/lo
    ln_split_kernel<<<MROWS, 256>>>(x1_, ln2g, ln2b, h2h_, h2l_);
    // 6) f1 = gelu(h2 @ W1^T + b1) -> hi/lo  (3-term)
    gemm_mma<<<dim3(FFDIM/128, MROWS/128), 256>>>(h2h_, h2l_, wh_+WOFF_1, wl_+WOFF_1, b1, nullptr, nullptr, f1h_, f1l_, MROWS, FFDIM, CATOM, 2, 3);
    // 7) out = x1 + f1 @ W2^T + b2  (3-term, fp32 to d_out)
    gemm_mma<<<dim3(CATOM/128, MROWS/128), 256>>>(f1h_, f1l_, wh_+WOFF_2, wl_+WOFF_2, b2, x1_, out, nullptr, nullptr, MROWS, CATOM, FFDIM, 1, 3);
}

// round 7
// speedup vs baseline: 3.2451x; 1.1046x over previous
#include <cuda_runtime.h>
#include <cuda_bf16.h>
#include <math.h>
#include <stdint.h>

#define CATOM 512
#define NHEADS 8
#define HDIM 64
#define BATCH 2
#define LSEQ 512
#define NATOMS 4
#define SEQ (LSEQ*NATOMS)      /* 2048 */
#define MROWS (BATCH*SEQ)      /* 4096 */
#define FFDIM 2048

// ---------------- scratch (device globals: allocation-free) ----------------
__device__ __nv_bfloat16 g_hh [MROWS*CATOM];
__device__ __nv_bfloat16 g_qb [MROWS*CATOM];
__device__ __nv_bfloat16 g_kb [MROWS*CATOM];
__device__ __nv_bfloat16 g_vb [MROWS*CATOM];
__device__ __nv_bfloat16 g_aoh[MROWS*CATOM];
__device__ float         g_x1 [MROWS*CATOM];
__device__ __nv_bfloat16 g_h2h[MROWS*CATOM], g_h2l[MROWS*CATOM];
__device__ __nv_bfloat16 g_f1h[MROWS*FFDIM], g_f1l[MROWS*FFDIM];
#define WOFF_Q 0
#define WOFF_K (CATOM*CATOM)
#define WOFF_V (2*CATOM*CATOM)
#define WOFF_O (3*CATOM*CATOM)
#define WOFF_1 (4*CATOM*CATOM)
#define WOFF_2 (4*CATOM*CATOM + FFDIM*CATOM)
#define WTOT   (4*CATOM*CATOM + 2*FFDIM*CATOM)
__device__ __nv_bfloat16 g_wh[WTOT], g_wl[WTOT];

// ======================= helpers =======================
__device__ __forceinline__ uint32_t smem_u32(const void* p) {
    uint32_t a;
    asm("{ .reg .u64 t; cvta.to.shared.u64 t, %1; cvt.u32.u64 %0, t; }" : "=r"(a) : "l"(p));
    return a;
}
__device__ __forceinline__ void cpa16(uint32_t d, const void* g) {
    asm volatile("cp.async.cg.shared.global [%0], [%1], 16;" :: "r"(d), "l"(g));
}
#define CPA_COMMIT() asm volatile("cp.async.commit_group;" ::: "memory")
#define CPA_WAIT1()  asm volatile("cp.async.wait_group 1;" ::: "memory")
#define CPA_WAIT0()  asm volatile("cp.async.wait_group 0;" ::: "memory")

__device__ __forceinline__ void ldm_x4(uint32_t* r, uint32_t addr) {
    asm volatile("ldmatrix.sync.aligned.m8n8.x4.shared.b16 {%0,%1,%2,%3}, [%4];"
        : "=r"(r[0]), "=r"(r[1]), "=r"(r[2]), "=r"(r[3]) : "r"(addr));
}
__device__ __forceinline__ void ldm_x4_t(uint32_t* r, uint32_t addr) {
    asm volatile("ldmatrix.sync.aligned.m8n8.x4.trans.shared.b16 {%0,%1,%2,%3}, [%4];"
        : "=r"(r[0]), "=r"(r[1]), "=r"(r[2]), "=r"(r[3]) : "r"(addr));
}
__device__ __forceinline__ void mma_bf16(float* d, const uint32_t* a, uint32_t b0, uint32_t b1) {
    asm volatile("mma.sync.aligned.m16n8k16.row.col.f32.bf16.bf16.f32 "
        "{%0,%1,%2,%3}, {%4,%5,%6,%7}, {%8,%9}, {%0,%1,%2,%3};"
        : "+f"(d[0]), "+f"(d[1]), "+f"(d[2]), "+f"(d[3])
        : "r"(a[0]), "r"(a[1]), "r"(a[2]), "r"(a[3]), "r"(b0), "r"(b1));
}
__device__ __forceinline__ uint32_t pack_bf16(float lo, float hi) {
    uint32_t d;
    asm("cvt.rn.bf16x2.f32 %0, %1, %2;" : "=r"(d) : "f"(hi), "f"(lo));
    return d;
}

// ======================= fused weight hi/lo split (all 6) ==================
#define WSEG (CATOM*CATOM)
#define WFF  (FFDIM*CATOM)
__global__ void __launch_bounds__(256) split6_kernel(
        const float* __restrict__ w0, const float* __restrict__ w1,
        const float* __restrict__ w2, const float* __restrict__ w3,
        const float* __restrict__ w4, const float* __restrict__ w5,
        __nv_bfloat16* __restrict__ hi, __nv_bfloat16* __restrict__ lo) {
    int i = blockIdx.x * blockDim.x + threadIdx.x;      // float4 index
    long e = (long)i * 4;
    const float* src;
    long off;
    if (e < 4L*WSEG) {
        int seg = (int)(e / WSEG);
        src = (seg == 0) ? w0 : (seg == 1) ? w1 : (seg == 2) ? w2 : w3;
        off = e - (long)seg * WSEG;
    } else if (e < 4L*WSEG + WFF) { src = w4; off = e - 4L*WSEG; }
    else                          { src = w5; off = e - 4L*WSEG - WFF; }
    float4 v = *(const float4*)(src + off);
    __nv_bfloat16 h0 = __float2bfloat16(v.x), h1 = __float2bfloat16(v.y);
    __nv_bfloat16 h2 = __float2bfloat16(v.z), h3 = __float2bfloat16(v.w);
    hi[e+0] = h0; hi[e+1] = h1; hi[e+2] = h2; hi[e+3] = h3;
    lo[e+0] = __float2bfloat16(v.x - __bfloat162float(h0));
    lo[e+1] = __float2bfloat16(v.y - __bfloat162float(h1));
    lo[e+2] = __float2bfloat16(v.z - __bfloat162float(h2));
    lo[e+3] = __float2bfloat16(v.w - __bfloat162float(h3));
}

// ======================= LayerNorm -> bf16 (hi, optional lo) ===============
__global__ void __launch_bounds__(256) ln_split_kernel(const float* __restrict__ x,
                                                       const float* __restrict__ g,
                                                       const float* __restrict__ b,
                                                       __nv_bfloat16* __restrict__ hi,
                                                       __nv_bfloat16* __restrict__ lo) {
    int row = blockIdx.x, tid = threadIdx.x;
    const float* xr = x + (size_t)row * CATOM;
    float v0 = xr[tid], v1 = xr[tid + 256];
    float s = v0 + v1, sq = v0*v0 + v1*v1;
    #pragma unroll
    for (int o = 16; o > 0; o >>= 1) {
        s  += __shfl_xor_sync(0xffffffffu, s,  o);
        sq += __shfl_xor_sync(0xffffffffu, sq, o);
    }
    __shared__ float ss[8], sqs[8];
    int w = tid >> 5;
    if ((tid & 31) == 0) { ss[w] = s; sqs[w] = sq; }
    __syncthreads();
    float tot = 0.f, totq = 0.f;
    #pragma unroll
    for (int i = 0; i < 8; i++) { tot += ss[i]; totq += sqs[i]; }
    float mu = tot * (1.0f/CATOM);
    float inv = rsqrtf(totq * (1.0f/CATOM) - mu*mu + 1e-5f);
    size_t o0 = (size_t)row * CATOM;
    float y0 = (v0 - mu) * inv * g[tid] + b[tid];
    float y1 = (v1 - mu) * inv * g[tid+256] + b[tid+256];
    __nv_bfloat16 h0 = __float2bfloat16(y0), h1 = __float2bfloat16(y1);
    hi[o0 + tid] = h0;
    hi[o0 + tid + 256] = h1;
    if (lo) {
        lo[o0 + tid]       = __float2bfloat16(y0 - __bfloat162float(h0));
        lo[o0 + tid + 256] = __float2bfloat16(y1 - __bfloat162float(h1));
    }
}

// ======================= pipelined mma.sync GEMM ===========================
// terms==3: AhBh+AhBl+AlBh   terms==2: AhBh+AhBl (Al unused)
// mode 0: Yf=.+bias  1: Yf=.+bias+resid  2: (Yh,Yl)=gelu(.+bias)  3: Yh=bf16(.+bias)
#define KC 32
#define LDS 40
#define TILE_E (128*LDS)          /* 5120 bf16 per tile */
#define GEMM_SMEM_B (2*4*TILE_E*2) /* 2 bufs x 4 tiles x 5120 x 2B = 81920 */

__device__ __forceinline__ void gemm_issue(__nv_bfloat16* base,
        const __nv_bfloat16* Ah, const __nv_bfloat16* Al,
        const __nv_bfloat16* Bh, const __nv_bfloat16* Bl,
        int m0, int n0, int k0, int K, int tid, int terms) {
    #pragma unroll
    for (int t = 0; t < 2; t++) {
        int idx = tid + t * 256;
        int r = idx >> 2, seg = (idx & 3) * 8;
        size_t ga = (size_t)(m0 + r) * K + k0 + seg;
        size_t gb = (size_t)(n0 + r) * K + k0 + seg;
        int so = r * LDS + seg;
        cpa16(smem_u32(base + 0*TILE_E + so), Ah + ga);
        if (terms == 3) cpa16(smem_u32(base + 1*TILE_E + so), Al + ga);
        cpa16(smem_u32(base + 2*TILE_E + so), Bh + gb);
        cpa16(smem_u32(base + 3*TILE_E + so), Bl + gb);
    }
    CPA_COMMIT();
}

__global__ void __launch_bounds__(256)
gemm_mma(const __nv_bfloat16* __restrict__ Ah, const __nv_bfloat16* __restrict__ Al,
         const __nv_bfloat16* __restrict__ Bh, const __nv_bfloat16* __restrict__ Bl,
         const float* __restrict__ bias, const float* __restrict__ resid,
         float* __restrict__ Yf, __nv_bfloat16* __restrict__ Yh, __nv_bfloat16* __restrict__ Yl,
         int M, int N, int K, int mode, int terms) {
    extern __shared__ __align__(16) __nv_bfloat16 smg[];

    int tid = threadIdx.x, wid = tid >> 5, lane = tid & 31;
    int n0 = blockIdx.x * 128, m0 = blockIdx.y * 128;
    int wr = wid >> 1, wc = wid & 1;
    int mb = wr * 32, nb = wc * 64;

    float acc[2][8][4];
    #pragma unroll
    for (int mt = 0; mt < 2; mt++)
        #pragma unroll
        for (int nt = 0; nt < 8; nt++)
            #pragma unroll
            for (int i = 0; i < 4; i++) acc[mt][nt][i] = 0.f;

    int lrow = lane & 15, lcol = (lane >> 4) * 8;
    const int nch = K / KC;

    gemm_issue(smg, Ah, Al, Bh, Bl, m0, n0, 0, K, tid, terms);

    for (int c = 0; c < nch; c++) {
        int buf = c & 1;
        if (c + 1 < nch) {
            gemm_issue(smg + (buf^1)*4*TILE_E, Ah, Al, Bh, Bl, m0, n0, (c+1)*KC, K, tid, terms);
            CPA_WAIT1();
        } else {
            CPA_WAIT0();
        }
        __syncthreads();

        __nv_bfloat16* base = smg + buf*4*TILE_E;
        __nv_bfloat16* pAh = base;
        __nv_bfloat16* pAl = base + TILE_E;
        __nv_bfloat16* pBh = base + 2*TILE_E;
        __nv_bfloat16* pBl = base + 3*TILE_E;

        #pragma unroll
        for (int ks = 0; ks < 2; ks++) {
            uint32_t ah[2][4], al[2][4];
            #pragma unroll
            for (int mt = 0; mt < 2; mt++) {
                int row = mb + mt*16 + lrow, col = ks*16 + lcol;
                ldm_x4(ah[mt], smem_u32(pAh + row*LDS + col));
                if (terms == 3) ldm_x4(al[mt], smem_u32(pAl + row*LDS + col));
            }
            #pragma unroll
            for (int nbk = 0; nbk < 4; nbk++) {
                uint32_t bh[4], bl[4];
                int row = nb + nbk*16 + lrow, col = ks*16 + lcol;
                ldm_x4(bh, smem_u32(pBh + row*LDS + col));
                ldm_x4(bl, smem_u32(pBl + row*LDS + col));
                #pragma unroll
                for (int wch = 0; wch < 2; wch++) {
                    int nt = nbk*2 + wch;
                    #pragma unroll
                    for (int mt = 0; mt < 2; mt++) {
                        mma_bf16(acc[mt][nt], ah[mt], bh[wch], bh[wch+2]);
                        mma_bf16(acc[mt][nt], ah[mt], bl[wch], bl[wch+2]);
                        if (terms == 3) mma_bf16(acc[mt][nt], al[mt], bh[wch], bh[wch+2]);
                    }
                }
            }
        }
        __syncthreads();
    }

    int g = lane >> 2, tig = lane & 3;
    #pragma unroll
    for (int mt = 0; mt < 2; mt++) {
        #pragma unroll
        for (int half = 0; half < 2; half++) {
            int m = m0 + mb + mt*16 + g + half*8;
            size_t mrow = (size_t)m * N;
            #pragma unroll
            for (int nt = 0; nt < 8; nt++) {
                int n = n0 + nb + nt*8 + tig*2;
                float v0 = acc[mt][nt][half*2+0] + bias[n];
                float v1 = acc[mt][nt][half*2+1] + bias[n+1];
                if (mode == 2) {
                    v0 = 0.5f * v0 * (1.0f + erff(v0 * 0.70710678118654752f));
                    v1 = 0.5f * v1 * (1.0f + erff(v1 * 0.70710678118654752f));
                    __nv_bfloat16 h0 = __float2bfloat16(v0), h1 = __float2bfloat16(v1);
                    Yh[mrow + n]   = h0; Yl[mrow + n]   = __float2bfloat16(v0 - __bfloat162float(h0));
                    Yh[mrow + n+1] = h1; Yl[mrow + n+1] = __float2bfloat16(v1 - __bfloat162float(h1));
                } else if (mode == 3) {
                    __nv_bfloat162 hv;
                    hv.x = __float2bfloat16(v0); hv.y = __float2bfloat16(v1);
                    *(__nv_bfloat162*)(Yh + mrow + n) = hv;
                } else {
                    if (mode == 1) {
                        float2 rv = *(const float2*)(resid + mrow + n);
                        v0 += rv.x; v1 += rv.y;
                    }
                    *(float2*)(Yf + mrow + n) = make_float2(v0, v1);
                }
            }
        }
    }
}

// ================= Flash attention, mma.sync bf16, cp.async pipelined ======
// grid (SEQ/128, B*H), 256 thr (8 warps). Warp w: q rows w*16..w*16+15.
#define AP 72
#define AQ_E (128*AP)
#define AKV_E (64*AP)
#define ATTN_SMEM_B ((AQ_E + 4*AKV_E)*2)   /* 55296 bytes */

__device__ __forceinline__ void attn_issue(__nv_bfloat16* kd, __nv_bfloat16* vd,
        const __nv_bfloat16* kb, const __nv_bfloat16* vb,
        size_t base, int j0, int tid) {
    #pragma unroll
    for (int i = 0; i < 2; i++) {
        int u = tid + i * 256;
        int r = u >> 3, seg = (u & 7) * 8;
        size_t gk = base + (size_t)(j0 + r) * CATOM + seg;
        cpa16(smem_u32(kd + r*AP + seg), kb + gk);
        cpa16(smem_u32(vd + r*AP + seg), vb + gk);
    }
    CPA_COMMIT();
}

__global__ void __launch_bounds__(256)
attn_mma(const __nv_bfloat16* __restrict__ qb, const __nv_bfloat16* __restrict__ kb,
         const __nv_bfloat16* __restrict__ vb, const float* __restrict__ pair_bias,
         const int* __restrict__ mask, __nv_bfloat16* __restrict__ outb) {
    extern __shared__ __align__(16) __nv_bfloat16 sma[];
    __nv_bfloat16* sQ = sma;

    int q0 = blockIdx.x * 128;
    int bh = blockIdx.y;
    int b = bh >> 3, h = bh & 7;
    int tid = threadIdx.x, wid = tid >> 5, lane = tid & 31;
    int g = lane >> 2, tig = lane & 3;
    int lrow = lane & 15, lcol = (lane >> 4) * 8;
    const float scale = 0.125f;
    size_t base = (size_t)b * SEQ * CATOM + (size_t)h * HDIM;

    // prologue: Q tile via cp.async (group 0)
    #pragma unroll
    for (int i = 0; i < 4; i++) {
        int u = tid + i * 256;
        int r = u >> 3, seg = (u & 7) * 8;
        cpa16(smem_u32(sQ + r*AP + seg), qb + base + (size_t)(q0 + r) * CATOM + seg);
    }
    CPA_COMMIT();
    // KV chunk 0 (group 1)
    attn_issue(sQ + AQ_E, sQ + AQ_E + AKV_E, kb, vb, base, 0, tid);
    CPA_WAIT1();           // Q done; KV0 may still be in flight
    __syncthreads();

    // hoist Q fragments
    uint32_t aQ[4][4];
    #pragma unroll
    for (int ks = 0; ks < 4; ks++)
        ldm_x4(aQ[ks], smem_u32(sQ + (wid*16 + lrow)*AP + ks*16 + lcol));

    float bias2[2];
    bias2[0] = pair_bias[h*16 + (g&3)*4 + ((2*tig)&3)];
    bias2[1] = pair_bias[h*16 + (g&3)*4 + ((2*tig+1)&3)];

    float mi[2] = {-1e30f, -1e30f}, li[2] = {0.f, 0.f};
    float acc[8][4];
    #pragma unroll
    for (int nt = 0; nt < 8; nt++)
        #pragma unroll
        for (int i = 0; i < 4; i++) acc[nt][i] = 0.f;

    const int* mrow = mask + (size_t)b * LSEQ;
    int msel = tig >> 1;
    int vkey = (lane & 7) | ((lane & 16) >> 1);
    int vcol = lane & 8;

    const int NJ = SEQ / 64;   // 32
    for (int c = 0; c < NJ; c++) {
        int buf = c & 1;
        if (c + 1 < NJ) {
            attn_issue(sQ + AQ_E + (buf^1)*2*AKV_E, sQ + AQ_E + (buf^1)*2*AKV_E + AKV_E,
                       kb, vb, base, (c+1)*64, tid);
            CPA_WAIT1();
        } else {
            CPA_WAIT0();
        }
        __syncthreads();
        __nv_bfloat16* sK = sQ + AQ_E + buf*2*AKV_E;
        __nv_bfloat16* sV = sK + AKV_E;
        int j0 = c * 64;

        // ---- scores ----
        float cc_[8][4];
        #pragma unroll
        for (int nt = 0; nt < 8; nt++)
            #pragma unroll
            for (int i = 0; i < 4; i++) cc_[nt][i] = 0.f;
        #pragma unroll
        for (int nbk = 0; nbk < 4; nbk++) {
            uint32_t bk[4][4];
            #pragma unroll
            for (int ks = 0; ks < 4; ks++)
                ldm_x4(bk[ks], smem_u32(sK + (nbk*16 + lrow)*AP + ks*16 + lcol));
            #pragma unroll
            for (int wch = 0; wch < 2; wch++) {
                float* cc = cc_[nbk*2 + wch];
                #pragma unroll
                for (int ks = 0; ks < 4; ks++)
                    mma_bf16(cc, aQ[ks], bk[ks][wch], bk[ks][wch+2]);
            }
        }

        // ---- scale + bias + mask ----
        #pragma unroll
        for (int nt = 0; nt < 8; nt++) {
            float mk = mrow[(j0 >> 2) + 2*nt + msel] ? 0.f : -1e30f;
            cc_[nt][0] = cc_[nt][0]*scale + bias2[0] + mk;
            cc_[nt][1] = cc_[nt][1]*scale + bias2[1] + mk;
            cc_[nt][2] = cc_[nt][2]*scale + bias2[0] + mk;
            cc_[nt][3] = cc_[nt][3]*scale + bias2[1] + mk;
        }

        // ---- online softmax ----
        float tm0 = -1e30f, tm1 = -1e30f;
        #pragma unroll
        for (int nt = 0; nt < 8; nt++) {
            tm0 = fmaxf(tm0, fmaxf(cc_[nt][0], cc_[nt][1]));
            tm1 = fmaxf(tm1, fmaxf(cc_[nt][2], cc_[nt][3]));
        }
        #pragma unroll
        for (int o = 1; o <= 2; o <<= 1) {
            tm0 = fmaxf(tm0, __shfl_xor_sync(0xffffffffu, tm0, o));
            tm1 = fmaxf(tm1, __shfl_xor_sync(0xffffffffu, tm1, o));
        }
        float mn0 = fmaxf(mi[0], tm0), mn1 = fmaxf(mi[1], tm1);
        float cor0 = __expf(mi[0] - mn0), cor1 = __expf(mi[1] - mn1);
        float sum0 = 0.f, sum1 = 0.f;
        #pragma unroll
        for (int nt = 0; nt < 8; nt++) {
            cc_[nt][0] = __expf(cc_[nt][0] - mn0);
            cc_[nt][1] = __expf(cc_[nt][1] - mn0);
            cc_[nt][2] = __expf(cc_[nt][2] - mn1);
            cc_[nt][3] = __expf(cc_[nt][3] - mn1);
            sum0 += cc_[nt][0] + cc_[nt][1];
            sum1 += cc_[nt][2] + cc_[nt][3];
        }
        #pragma unroll
        for (int o = 1; o <= 2; o <<= 1) {
            sum0 += __shfl_xor_sync(0xffffffffu, sum0, o);
            sum1 += __shfl_xor_sync(0xffffffffu, sum1, o);
        }
        li[0] = li[0]*cor0 + sum0; li[1] = li[1]*cor1 + sum1;
        mi[0] = mn0; mi[1] = mn1;
        #pragma unroll
        for (int nt = 0; nt < 8; nt++) {
            acc[nt][0] *= cor0; acc[nt][1] *= cor0;
            acc[nt][2] *= cor1; acc[nt][3] *= cor1;
        }

        // ---- pack P ----
        uint32_t aP[4][4];
        #pragma unroll
        for (int ks = 0; ks < 4; ks++) {
            aP[ks][0] = pack_bf16(cc_[2*ks][0],   cc_[2*ks][1]);
            aP[ks][1] = pack_bf16(cc_[2*ks][2],   cc_[2*ks][3]);
            aP[ks][2] = pack_bf16(cc_[2*ks+1][0], cc_[2*ks+1][1]);
            aP[ks][3] = pack_bf16(cc_[2*ks+1][2], cc_[2*ks+1][3]);
        }

        // ---- O += P @ V ----
        #pragma unroll
        for (int nbk = 0; nbk < 4; nbk++) {
            uint32_t bv[4][4];
            #pragma unroll
            for (int ks = 0; ks < 4; ks++)
                ldm_x4_t(bv[ks], smem_u32(sV + (ks*16 + vkey)*AP + nbk*16 + vcol));
            #pragma unroll
            for (int wch = 0; wch < 2; wch++) {
                float* oo = acc[nbk*2 + wch];
                #pragma unroll
                for (int ks = 0; ks < 4; ks++)
                    mma_bf16(oo, aP[ks], bv[ks][wch], bv[ks][wch+2]);
            }
        }
        __syncthreads();
    }

    // ---- epilogue ----
    float inv0 = 1.0f / li[0], inv1 = 1.0f / li[1];
    #pragma unroll
    for (int nt = 0; nt < 8; nt++) {
        size_t r0 = base + (size_t)(q0 + wid*16 + g) * CATOM + nt*8 + tig*2;
        size_t r1 = r0 + (size_t)8 * CATOM;
        __nv_bfloat162 v0, v1;
        v0.x = __float2bfloat16(acc[nt][0] * inv0);
        v0.y = __float2bfloat16(acc[nt][1] * inv0);
        v1.x = __float2bfloat16(acc[nt][2] * inv1);
        v1.y = __float2bfloat16(acc[nt][3] * inv1);
        *(__nv_bfloat162*)(outb + r0) = v0;
        *(__nv_bfloat162*)(outb + r1) = v1;
    }
}

// ---------------- driver ----------------
extern "C" void kernel_launch(void* const* d_in, const int* in_sizes, int n_in,
                              void* d_out, int out_size) {
    const float* atom = (const float*)d_in[0];
    const int* mask = (const int*)d_in[1];
    const float* ln1g = (const float*)d_in[2];
    const float* ln1b = (const float*)d_in[3];
    const float* Wq = (const float*)d_in[4];
    const float* bq = (const float*)d_in[5];
    const float* Wk = (const float*)d_in[6];
    const float* bk = (const float*)d_in[7];
    const float* Wv = (const float*)d_in[8];
    const float* bv = (const float*)d_in[9];
    const float* Wo = (const float*)d_in[10];
    const float* bo = (const float*)d_in[11];
    const float* pb = (const float*)d_in[12];
    const float* ln2g = (const float*)d_in[13];
    const float* ln2b = (const float*)d_in[14];
    const float* W1 = (const float*)d_in[15];
    const float* b1 = (const float*)d_in[16];
    const float* W2 = (const float*)d_in[17];
    const float* b2 = (const float*)d_in[18];
    float* out = (float*)d_out;

    __nv_bfloat16 *hh_, *qb_, *kb_, *vb_, *aoh_, *h2h_, *h2l_, *f1h_, *f1l_, *wh_, *wl_;
    float *x1_;
    cudaGetSymbolAddress((void**)&hh_,  g_hh);
    cudaGetSymbolAddress((void**)&qb_,  g_qb);
    cudaGetSymbolAddress((void**)&kb_,  g_kb);
    cudaGetSymbolAddress((void**)&vb_,  g_vb);
    cudaGetSymbolAddress((void**)&aoh_, g_aoh);
    cudaGetSymbolAddress((void**)&x1_,  g_x1);
    cudaGetSymbolAddress((void**)&h2h_, g_h2h); cudaGetSymbolAddress((void**)&h2l_, g_h2l);
    cudaGetSymbolAddress((void**)&f1h_, g_f1h); cudaGetSymbolAddress((void**)&f1l_, g_f1l);
    cudaGetSymbolAddress((void**)&wh_,  g_wh);  cudaGetSymbolAddress((void**)&wl_,  g_wl);

    cudaFuncSetAttribute(gemm_mma, cudaFuncAttributeMaxDynamicSharedMemorySize, GEMM_SMEM_B);
    cudaFuncSetAttribute(attn_mma, cudaFuncAttributeMaxDynamicSharedMemorySize, ATTN_SMEM_B);

    // fused weight splits
    split6_kernel<<<WTOT/4/256, 256>>>(Wq, Wk, Wv, Wo, W1, W2, wh_, wl_);

    // 1) h = LN1(x) -> single bf16
    ln_split_kernel<<<MROWS, 256>>>(atom, ln1g, ln1b, hh_, nullptr);
    // 2) q,k,v bf16 (2-term)
    gemm_mma<<<dim3(CATOM/128, MROWS/128), 256, GEMM_SMEM_B>>>(hh_, nullptr, wh_+WOFF_Q, wl_+WOFF_Q, bq, nullptr, nullptr, qb_, nullptr, MROWS, CATOM, CATOM, 3, 2);
    gemm_mma<<<dim3(CATOM/128, MROWS/128), 256, GEMM_SMEM_B>>>(hh_, nullptr, wh_+WOFF_K, wl_+WOFF_K, bk, nullptr, nullptr, kb_, nullptr, MROWS, CATOM, CATOM, 3, 2);
    gemm_mma<<<dim3(CATOM/128, MROWS/128), 256, GEMM_SMEM_B>>>(hh_, nullptr, wh_+WOFF_V, wl_+WOFF_V, bv, nullptr, nullptr, vb_, nullptr, MROWS, CATOM, CATOM, 3, 2);
    // 3) attention (tensor core, pipelined)
    attn_mma<<<dim3(SEQ/128, BATCH*NHEADS), 256, ATTN_SMEM_B>>>(qb_, kb_, vb_, pb, mask, aoh_);
    // 4) x1 = x + ao @ Wo^T + bo  (2-term, fp32)
    gemm_mma<<<dim3(CATOM/128, MROWS/128), 256, GEMM_SMEM_B>>>(aoh_, nullptr, wh_+WOFF_O, wl_+WOFF_O, bo, atom, x1_, nullptr, nullptr, MROWS, CATOM, CATOM, 1, 2);
    // 5) h2 = LN2(x1) -> hi/lo
    ln_split_kernel<<<MROWS, 256>>>(x1_, ln2g, ln2b, h2h_, h2l_);
    // 6) f1 = gelu(h2 @ W1^T + b1) -> hi/lo  (3-term)
    gemm_mma<<<dim3(FFDIM/128, MROWS/128), 256, GEMM_SMEM_B>>>(h2h_, h2l_, wh_+WOFF_1, wl_+WOFF_1, b1, nullptr, nullptr, f1h_, f1l_, MROWS, FFDIM, CATOM, 2, 3);
    // 7) out = x1 + f1 @ W2^T + b2  (3-term, fp32 to d_out)
    gemm_mma<<<dim3(CATOM/128, MROWS/128), 256, GEMM_SMEM_B>>>(f1h_, f1l_, wh_+WOFF_2, wl_+WOFF_2, b2, x1_, out, nullptr, nullptr, MROWS, CATOM, FFDIM, 1, 3);
}